// round 8
// baseline (speedup 1.0000x reference)
#include <cuda_runtime.h>
#include <cstdint>
#include <math.h>

#define B_  2
#define T_  2048
#define D_  2048
#define H_  32
#define HD_ 64

// ---------------- scratch (no allocation allowed) ----------------
static __device__ int g_mode;
static __device__ __align__(16) int8_t g_hs[B_*T_*D_];
static __device__ __align__(16) int8_t g_Wq[D_*D_];
static __device__ __align__(16) int8_t g_Wk[D_*D_];
static __device__ __align__(16) int8_t g_Wv[D_*D_];
static __device__ __align__(16) int8_t g_Wo[D_*D_];
static __device__ __align__(16) int8_t g_bq[D_];
static __device__ __align__(16) int8_t g_bk[D_];
static __device__ __align__(16) int8_t g_bv[D_];
static __device__ __align__(16) int8_t g_q [B_*T_*D_];
static __device__ __align__(16) int8_t g_k [B_*T_*D_];
static __device__ __align__(16) int8_t g_v [B_*T_*D_];
static __device__ __align__(16) int8_t g_ao[B_*T_*D_];

// ---------------- dtype sniff (proven) ----------------
__global__ void sniff_kernel(const void* __restrict__ p)
{
    __shared__ int s_i32, s_f32;
    if (threadIdx.x == 0) { s_i32 = 1; s_f32 = 1; }
    __syncthreads();
    const int*   wi = (const int*)p;
    const float* wf = (const float*)p;
    int ok_i = 1, ok_f = 1;
    for (int i = threadIdx.x; i < 4096; i += blockDim.x) {
        int v = wi[i];
        if (v < -128 || v > 127) ok_i = 0;
        float f = wf[i];
        if (!(f >= -128.f && f <= 127.f && f == rintf(f))) ok_f = 0;
    }
    if (!ok_i) atomicExch(&s_i32, 0);
    if (!ok_f) atomicExch(&s_f32, 0);
    __syncthreads();
    if (threadIdx.x == 0) g_mode = s_i32 ? 1 : (s_f32 ? 2 : 0);
}

// ---------------- pack helpers (proven logic) ----------------
__device__ __forceinline__ void pack_one(const void* in, int* ow, int nwords, int mode)
{
    int i = blockIdx.x * blockDim.x + threadIdx.x;
    const int stride = gridDim.x * blockDim.x;
    for (; i < nwords; i += stride) {
        int w;
        if (mode == 0) {
            w = ((const int*)in)[i];
        } else if (mode == 1) {
            int4 v = ((const int4*)in)[i];
            w = (v.x & 255) | ((v.y & 255) << 8) | ((v.z & 255) << 16) | ((v.w & 255) << 24);
        } else {
            float4 v = ((const float4*)in)[i];
            int a = (int)rintf(v.x) & 255, b = (int)rintf(v.y) & 255;
            int c = (int)rintf(v.z) & 255, d = (int)rintf(v.w) & 255;
            w = a | (b << 8) | (c << 16) | (d << 24);
        }
        ow[i] = w;
    }
}
__global__ void pack_bias_kernel(const void* pq, const void* pk, const void* pv)
{
    const int sel = blockIdx.y;
    const void* in = (sel == 0) ? pq : (sel == 1) ? pk : pv;
    int* ow = (int*)((sel == 0) ? g_bq : (sel == 1) ? g_bk : g_bv);
    pack_one(in, ow, D_ / 4, g_mode);
}
__global__ void pack_main_kernel(const void* p0, const void* p1, const void* p2,
                                 const void* p3, const void* p4)
{
    const int sel = blockIdx.y;
    const void* in = (sel == 0) ? p0 : (sel == 1) ? p1 : (sel == 2) ? p2 :
                     (sel == 3) ? p3 : p4;
    int* ow = (int*)((sel == 0) ? g_hs : (sel == 1) ? g_Wq : (sel == 2) ? g_Wk :
                     (sel == 3) ? g_Wv : g_Wo);
    const int nwords = (sel == 0) ? (B_*T_*D_/4) : (D_*D_/4);
    pack_one(in, ow, nwords, g_mode);
}

// ---------------- mma / ldmatrix / cp.async helpers ----------------
__device__ __forceinline__ void mma_s8(int& d0, int& d1, int& d2, int& d3,
                                       int a0, int a1, int a2, int a3,
                                       int b0, int b1)
{
    asm volatile(
        "mma.sync.aligned.m16n8k32.row.col.s32.s8.s8.s32 "
        "{%0,%1,%2,%3},{%4,%5,%6,%7},{%8,%9},{%0,%1,%2,%3};\n"
        : "+r"(d0), "+r"(d1), "+r"(d2), "+r"(d3)
        : "r"(a0), "r"(a1), "r"(a2), "r"(a3), "r"(b0), "r"(b1));
}
__device__ __forceinline__ void ldsm4(int& r0, int& r1, int& r2, int& r3, uint32_t a)
{
    asm volatile("ldmatrix.sync.aligned.m8n8.x4.shared.b16 {%0,%1,%2,%3},[%4];\n"
                 : "=r"(r0), "=r"(r1), "=r"(r2), "=r"(r3) : "r"(a));
}
__device__ __forceinline__ void ldsm2(int& r0, int& r1, uint32_t a)
{
    asm volatile("ldmatrix.sync.aligned.m8n8.x2.shared.b16 {%0,%1},[%2];\n"
                 : "=r"(r0), "=r"(r1) : "r"(a));
}
__device__ __forceinline__ void cp16(uint32_t dst, const void* src)
{
    asm volatile("cp.async.cg.shared.global [%0],[%1],16;\n" :: "r"(dst), "l"(src));
}
__device__ __forceinline__ void cp_commit() { asm volatile("cp.async.commit_group;\n"); }
__device__ __forceinline__ void cp_wait0()  { asm volatile("cp.async.wait_group 0;\n"); }
__device__ __forceinline__ uint32_t s2u(const void* p)
{
    return (uint32_t)__cvta_generic_to_shared(p);
}

// ---------------- GEMM body (proven R3/R4) ----------------
// 128x128 tile, 256 thr (8 warps 2m x 4n), warp 64x32, BK=64B, double-buffered cp.async.
__device__ __forceinline__ void gemm_body(const float* __restrict__ bias_f,
                                          float alpha, float* __restrict__ outf,
                                          int zsel)
{
    __shared__ int As[2][128 * 20];
    __shared__ int Bs[2][128 * 20];

    const int tid = threadIdx.x, w = tid >> 5, lane = tid & 31;
    const int g = lane >> 2, tg = lane & 3;
    const int wm = w >> 2, wn = w & 3;
    const int m0 = blockIdx.y * 128, n0 = blockIdx.x * 128;

    const int4* X4 = (const int4*)((zsel == 3) ? (const void*)g_ao : (const void*)g_hs);
    const int4* W4 = (const int4*)((zsel == 0) ? (const void*)g_Wq :
                                   (zsel == 1) ? (const void*)g_Wk :
                                   (zsel == 2) ? (const void*)g_Wv : (const void*)g_Wo);

    const uint32_t asb = s2u(&As[0][0]);
    const uint32_t bsb = s2u(&Bs[0][0]);

    const uint32_t a_lrow = (uint32_t)(lane & 15);
    const uint32_t a_khalf = (uint32_t)(lane >> 4);
    const uint32_t offA = (uint32_t)((wm * 64 + a_lrow) * 20 + a_khalf * 4) * 4;
    const uint32_t b_lrow = (uint32_t)(lane & 7);
    const uint32_t b_khalf = (uint32_t)((lane >> 3) & 1);
    const uint32_t offB = (uint32_t)((wn * 32 + b_lrow) * 20 + b_khalf * 4) * 4;

    const int r_a = tid >> 2, c4_a = tid & 3;
    const int r_b = (tid + 256) >> 2;

    int acc[4][4][4];
    #pragma unroll
    for (int mt = 0; mt < 4; mt++)
        #pragma unroll
        for (int nt = 0; nt < 4; nt++)
            #pragma unroll
            for (int i = 0; i < 4; i++) acc[mt][nt][i] = 0;

    auto issue = [&](int kt, int buf) {
        uint32_t ab = asb + (uint32_t)buf * 128 * 20 * 4;
        uint32_t bb = bsb + (uint32_t)buf * 128 * 20 * 4;
        cp16(ab + (uint32_t)(r_a * 20 + c4_a * 4) * 4, X4 + (size_t)(m0 + r_a) * 128 + kt * 4 + c4_a);
        cp16(ab + (uint32_t)(r_b * 20 + c4_a * 4) * 4, X4 + (size_t)(m0 + r_b) * 128 + kt * 4 + c4_a);
        cp16(bb + (uint32_t)(r_a * 20 + c4_a * 4) * 4, W4 + (size_t)(n0 + r_a) * 128 + kt * 4 + c4_a);
        cp16(bb + (uint32_t)(r_b * 20 + c4_a * 4) * 4, W4 + (size_t)(n0 + r_b) * 128 + kt * 4 + c4_a);
        cp_commit();
    };

    issue(0, 0);
    for (int kt = 0; kt < 32; ++kt) {
        cp_wait0();
        __syncthreads();
        if (kt < 31) issue(kt + 1, (kt + 1) & 1);
        const uint32_t abuf = asb + (uint32_t)(kt & 1) * 128 * 20 * 4;
        const uint32_t bbuf = bsb + (uint32_t)(kt & 1) * 128 * 20 * 4;
        #pragma unroll
        for (int ks = 0; ks < 2; ++ks) {
            int a[4][4];
            #pragma unroll
            for (int mt = 0; mt < 4; mt++)
                ldsm4(a[mt][0], a[mt][1], a[mt][2], a[mt][3],
                      abuf + offA + (uint32_t)(mt * 16 * 20 + ks * 8) * 4);
            #pragma unroll
            for (int nt = 0; nt < 4; nt++) {
                int b0, b1;
                ldsm2(b0, b1, bbuf + offB + (uint32_t)(nt * 8 * 20 + ks * 8) * 4);
                #pragma unroll
                for (int mt = 0; mt < 4; mt++)
                    mma_s8(acc[mt][nt][0], acc[mt][nt][1], acc[mt][nt][2], acc[mt][nt][3],
                           a[mt][0], a[mt][1], a[mt][2], a[mt][3], b0, b1);
            }
        }
    }

    if (zsel < 3) {
        const int8_t* bi = (zsel == 0) ? g_bq : (zsel == 1) ? g_bk : g_bv;
        int8_t* Y = (zsel == 0) ? g_q : (zsel == 1) ? g_k : g_v;
        #pragma unroll
        for (int nt = 0; nt < 4; nt++) {
            int col = n0 + wn * 32 + nt * 8 + 2 * tg;
            float bb0 = (float)bi[col], bb1 = (float)bi[col + 1];
            #pragma unroll
            for (int mt = 0; mt < 4; mt++) {
                int r = m0 + wm * 64 + mt * 16 + g;
                #pragma unroll
                for (int half = 0; half < 2; half++) {
                    int rr = r + half * 8;
                    float y0 = __fadd_rn(__fmul_rn(alpha, (float)acc[mt][nt][half * 2 + 0]), bb0);
                    float y1 = __fadd_rn(__fmul_rn(alpha, (float)acc[mt][nt][half * 2 + 1]), bb1);
                    int q0 = max(-128, min(127, (int)rintf(y0)));
                    int q1 = max(-128, min(127, (int)rintf(y1)));
                    *(short*)&Y[(size_t)rr * D_ + col] = (short)((q0 & 255) | ((q1 & 255) << 8));
                }
            }
        }
    } else {
        #pragma unroll
        for (int nt = 0; nt < 4; nt++) {
            int col = n0 + wn * 32 + nt * 8 + 2 * tg;
            float bb0 = bias_f[col], bb1 = bias_f[col + 1];
            #pragma unroll
            for (int mt = 0; mt < 4; mt++) {
                int r = m0 + wm * 64 + mt * 16 + g;
                #pragma unroll
                for (int half = 0; half < 2; half++) {
                    int rr = r + half * 8;
                    float y0 = __fadd_rn(__fmul_rn(alpha, (float)acc[mt][nt][half * 2 + 0]), bb0);
                    float y1 = __fadd_rn(__fmul_rn(alpha, (float)acc[mt][nt][half * 2 + 1]), bb1);
                    *(float2*)&outf[(size_t)rr * D_ + col] = make_float2(y0, y1);
                }
            }
        }
    }
}

__global__ __launch_bounds__(256, 2) void gemm_qkv_kernel()
{
    gemm_body(nullptr, 3e-4f, nullptr, (int)blockIdx.z);
}
__global__ __launch_bounds__(256, 2) void gemm_out_kernel(const float* __restrict__ bo,
                                                          float* __restrict__ out)
{
    gemm_body(bo, 1e-4f, out, 3);
}

// ---------------- fused attention: 128 q-rows/block, 512 thr, 16 warps ----------------
// warp mapping: wm = w>>1 (8 groups of 16 rows), wn = w&1 (col half).
// Same per-warp footprint as the proven 64-row version; K/V staged once per 128 rows.
// dynamic smem layout (ints):
//   qs   [128*20]  @ 0
//   ks   [128*20]  @ 2560
//   vraw [128*20]  @ 5120
//   vT   [64*36]   @ 7680
//   ps   [128*36]  @ 9984
//   redm [2][128]  @ 14592 (float)
//   redl [2][128]  @ 14848 (float)
//   rowM [128]     @ 15104 (float)
//   rowRL[128]     @ 15232 (float)   total 15360 ints = 61440 B
#define ATTN_SMEM 61440

__global__ __launch_bounds__(512) void attn_kernel()
{
    const float A_QK = 2e-5f, A_PV = 1e-2f;
    const int bh = blockIdx.y, b = bh >> 5, h = bh & 31;
    const int r0 = blockIdx.x * 128;
    const int tid = threadIdx.x, w = tid >> 5, lane = tid & 31;
    const int g = lane >> 2, tg = lane & 3;
    const int wm = w >> 1, wn = w & 1;

    extern __shared__ int sm[];
    int* qs   = sm;
    int* ks   = sm + 2560;
    int* vraw = sm + 5120;
    int* vT   = sm + 7680;
    int* ps   = sm + 9984;
    float* redm  = (float*)(sm + 14592);
    float* redl  = (float*)(sm + 14848);
    float* rowM  = (float*)(sm + 15104);
    float* rowRL = (float*)(sm + 15232);

    const int4* Q4 = (const int4*)g_q;
    const int4* K4 = (const int4*)g_k;
    const int4* V4 = (const int4*)g_v;

    const uint32_t qsb = s2u(qs);
    const uint32_t ksb = s2u(ks);
    const uint32_t psb32 = s2u(ps);
    const uint32_t vtb = s2u(vT);

    const uint32_t a_lrow = (uint32_t)(lane & 15);
    const uint32_t a_khalf = (uint32_t)(lane >> 4);
    const uint32_t offQ  = (uint32_t)((wm * 16 + a_lrow) * 20 + a_khalf * 4) * 4;
    const uint32_t offPs = (uint32_t)((wm * 16 + a_lrow) * 36 + a_khalf * 4) * 4;
    const uint32_t b_lrow = (uint32_t)(lane & 7);
    const uint32_t b_khalf = (uint32_t)((lane >> 3) & 1);
    const uint32_t offK  = (uint32_t)(b_lrow * 20 + b_khalf * 4) * 4;
    const uint32_t offVt = (uint32_t)(b_lrow * 36 + b_khalf * 4) * 4;

    // q tile: 128 rows x 16 words = 512 int4, one per thread
    {
        int row = tid >> 2, c4 = tid & 3;
        *(int4*)&qs[row * 20 + c4 * 4] = Q4[(size_t)(b * T_ + r0 + row) * 128 + h * 4 + c4];
    }

    const int nch = ((r0 + 127) >> 7) + 1;
    const int tA = r0 + wm * 16 + g, tB = tA + 8;

    // ---------- pass A: online row stats ----------
    float mA = -1e30f, lA = 0.f, mB = -1e30f, lB = 0.f;
    for (int c = 0; c < nch; ++c) {
        const int s0 = c << 7;
        {
            int ra = tid >> 2, ca = tid & 3;
            *(int4*)&ks[ra * 20 + ca * 4] = K4[(size_t)(b * T_ + s0 + ra) * 128 + h * 4 + ca];
        }
        __syncthreads();

        int cc[8][4];
        #pragma unroll
        for (int nt = 0; nt < 8; nt++)
            #pragma unroll
            for (int i = 0; i < 4; i++) cc[nt][i] = 0;
        #pragma unroll
        for (int ksi = 0; ksi < 2; ++ksi) {
            int a0, a1, a2, a3;
            ldsm4(a0, a1, a2, a3, qsb + offQ + (uint32_t)(ksi * 8) * 4);
            #pragma unroll
            for (int nt = 0; nt < 8; nt++) {
                int b0, b1;
                ldsm2(b0, b1, ksb + offK + (uint32_t)((wn * 64 + nt * 8) * 20 + ksi * 8) * 4);
                mma_s8(cc[nt][0], cc[nt][1], cc[nt][2], cc[nt][3], a0, a1, a2, a3, b0, b1);
            }
        }
        #pragma unroll
        for (int nt = 0; nt < 8; nt++) {
            int scol = s0 + wn * 64 + nt * 8 + 2 * tg;
            #pragma unroll
            for (int e = 0; e < 2; e++) {
                int s = scol + e;
                if (s <= tA) {
                    float sc = __fmul_rn(A_QK, (float)cc[nt][e]);
                    float mn = fmaxf(mA, sc);
                    lA = lA * __expf(mA - mn) + __expf(sc - mn);
                    mA = mn;
                }
                if (s <= tB) {
                    float sc = __fmul_rn(A_QK, (float)cc[nt][2 + e]);
                    float mn = fmaxf(mB, sc);
                    lB = lB * __expf(mB - mn) + __expf(sc - mn);
                    mB = mn;
                }
            }
        }
        __syncthreads();
    }
    #pragma unroll
    for (int d = 1; d < 4; d <<= 1) {
        float mo = __shfl_xor_sync(0xffffffffu, mA, d);
        float lo = __shfl_xor_sync(0xffffffffu, lA, d);
        float mn = fmaxf(mA, mo);
        lA = lA * __expf(mA - mn) + lo * __expf(mo - mn); mA = mn;
        mo = __shfl_xor_sync(0xffffffffu, mB, d);
        lo = __shfl_xor_sync(0xffffffffu, lB, d);
        mn = fmaxf(mB, mo);
        lB = lB * __expf(mB - mn) + lo * __expf(mo - mn); mB = mn;
    }
    if (tg == 0) {
        redm[wn * 128 + wm * 16 + g] = mA;     redl[wn * 128 + wm * 16 + g] = lA;
        redm[wn * 128 + wm * 16 + g + 8] = mB; redl[wn * 128 + wm * 16 + g + 8] = lB;
    }
    __syncthreads();
    if (tid < 128) {
        float m0 = redm[tid], m1 = redm[128 + tid];
        float l0 = redl[tid], l1 = redl[128 + tid];
        float M = fmaxf(m0, m1);
        float L = l0 * __expf(m0 - M) + l1 * __expf(m1 - M);
        rowM[tid] = M;
        rowRL[tid] = 127.0f / L;
    }
    __syncthreads();

    const float MA = rowM[wm * 16 + g],     RA = rowRL[wm * 16 + g];
    const float MB = rowM[wm * 16 + g + 8], RB = rowRL[wm * 16 + g + 8];

    // ---------- pass B: recompute scores, quantize, PV ----------
    int oacc[4][4];
    #pragma unroll
    for (int nt = 0; nt < 4; nt++)
        #pragma unroll
        for (int i = 0; i < 4; i++) oacc[nt][i] = 0;

    for (int c = 0; c < nch; ++c) {
        const int s0 = c << 7;
        {
            int ra = tid >> 2, ca = tid & 3;
            size_t base = (size_t)(b * T_ + s0 + ra) * 128 + h * 4 + ca;
            *(int4*)&ks[ra * 20 + ca * 4]   = K4[base];
            *(int4*)&vraw[ra * 20 + ca * 4] = V4[base];
        }
        __syncthreads();

        int cc[8][4];
        #pragma unroll
        for (int nt = 0; nt < 8; nt++)
            #pragma unroll
            for (int i = 0; i < 4; i++) cc[nt][i] = 0;
        #pragma unroll
        for (int ksi = 0; ksi < 2; ++ksi) {
            int a0, a1, a2, a3;
            ldsm4(a0, a1, a2, a3, qsb + offQ + (uint32_t)(ksi * 8) * 4);
            #pragma unroll
            for (int nt = 0; nt < 8; nt++) {
                int b0, b1;
                ldsm2(b0, b1, ksb + offK + (uint32_t)((wn * 64 + nt * 8) * 20 + ksi * 8) * 4);
                mma_s8(cc[nt][0], cc[nt][1], cc[nt][2], cc[nt][3], a0, a1, a2, a3, b0, b1);
            }
        }
        char* psb = (char*)ps;
        #pragma unroll
        for (int nt = 0; nt < 8; nt++) {
            int col = wn * 64 + nt * 8 + 2 * tg;
            int scol = s0 + col;
            int pA0 = 0, pA1 = 0, pB0 = 0, pB1 = 0;
            if (scol <= tA) {
                float p = __expf(__fmul_rn(A_QK, (float)cc[nt][0]) - MA) * RA;
                pA0 = min(127, (int)rintf(p));
            }
            if (scol + 1 <= tA) {
                float p = __expf(__fmul_rn(A_QK, (float)cc[nt][1]) - MA) * RA;
                pA1 = min(127, (int)rintf(p));
            }
            if (scol <= tB) {
                float p = __expf(__fmul_rn(A_QK, (float)cc[nt][2]) - MB) * RB;
                pB0 = min(127, (int)rintf(p));
            }
            if (scol + 1 <= tB) {
                float p = __expf(__fmul_rn(A_QK, (float)cc[nt][3]) - MB) * RB;
                pB1 = min(127, (int)rintf(p));
            }
            *(short*)(psb + (wm * 16 + g) * 144 + col)     = (short)(pA0 | (pA1 << 8));
            *(short*)(psb + (wm * 16 + g + 8) * 144 + col) = (short)(pB0 | (pB1 << 8));
        }
        // transpose-pack V: vT[d][sw] packs v[s0+4sw..+3][d]; 2048 words, 512 thr x 4
        #pragma unroll
        for (int k = 0; k < 4; ++k) {
            int idx = k * 512 + tid;
            int d = idx >> 5, sw = idx & 31;
            int cword = d >> 2, csh = (d & 3) * 8;
            unsigned wd = 0;
            #pragma unroll
            for (int z = 0; z < 4; ++z) {
                unsigned by = ((unsigned)vraw[(4 * sw + z) * 20 + cword] >> csh) & 255u;
                wd |= by << (8 * z);
            }
            vT[d * 36 + sw] = (int)wd;
        }
        __syncthreads();

        #pragma unroll
        for (int kk = 0; kk < 4; ++kk) {
            int a0, a1, a2, a3;
            ldsm4(a0, a1, a2, a3, psb32 + offPs + (uint32_t)(kk * 8) * 4);
            #pragma unroll
            for (int nt = 0; nt < 4; nt++) {
                int b0, b1;
                ldsm2(b0, b1, vtb + offVt + (uint32_t)((wn * 32 + nt * 8) * 36 + kk * 8) * 4);
                mma_s8(oacc[nt][0], oacc[nt][1], oacc[nt][2], oacc[nt][3],
                       a0, a1, a2, a3, b0, b1);
            }
        }
        __syncthreads();
    }

    #pragma unroll
    for (int nt = 0; nt < 4; nt++) {
        int col = h * HD_ + wn * 32 + nt * 8 + 2 * tg;
        float yA0 = __fmul_rn(A_PV, (float)oacc[nt][0]);
        float yA1 = __fmul_rn(A_PV, (float)oacc[nt][1]);
        float yB0 = __fmul_rn(A_PV, (float)oacc[nt][2]);
        float yB1 = __fmul_rn(A_PV, (float)oacc[nt][3]);
        int qA0 = max(-128, min(127, (int)rintf(yA0)));
        int qA1 = max(-128, min(127, (int)rintf(yA1)));
        int qB0 = max(-128, min(127, (int)rintf(yB0)));
        int qB1 = max(-128, min(127, (int)rintf(yB1)));
        *(short*)&g_ao[(size_t)(b * T_ + tA) * D_ + col] = (short)((qA0 & 255) | ((qA1 & 255) << 8));
        *(short*)&g_ao[(size_t)(b * T_ + tB) * D_ + col] = (short)((qB0 & 255) | ((qB1 & 255) << 8));
    }
}

// ---------------- launch ----------------
extern "C" void kernel_launch(void* const* d_in, const int* in_sizes, int n_in,
                              void* d_out, int out_size)
{
    (void)n_in; (void)out_size;
    int i_hs, i_Wq, i_bq, i_Wk, i_bk, i_Wv, i_bv, i_Wo, i_bo;
    if (in_sizes[0] == 4194304) {          // alphabetical
        i_Wk = 0; i_Wo = 1; i_Wq = 2; i_Wv = 3;
        i_bk = 5; i_bo = 6; i_bq = 7; i_bv = 8; i_hs = 9;
    } else {                                // dict / signature order
        i_hs = 0; i_Wq = 2; i_bq = 3; i_Wk = 4; i_bk = 5;
        i_Wv = 6; i_bv = 7; i_Wo = 8; i_bo = 9;
    }
    const float* bo = (const float*)d_in[i_bo];
    float* out = (float*)d_out;

    cudaFuncSetAttribute(attn_kernel, cudaFuncAttributeMaxDynamicSharedMemorySize,
                         ATTN_SMEM);

    // ncu captures the 5th launch -> attn_kernel
    sniff_kernel<<<1, 256>>>(d_in[i_hs]);                                     // 1
    pack_bias_kernel<<<dim3(2, 3), 256>>>(d_in[i_bq], d_in[i_bk], d_in[i_bv]); // 2
    pack_main_kernel<<<dim3(512, 5), 256>>>(d_in[i_hs], d_in[i_Wq], d_in[i_Wk],
                                            d_in[i_Wv], d_in[i_Wo]);          // 3
    dim3 gg(D_ / 128, (B_ * T_) / 128);
    gemm_qkv_kernel<<<dim3(D_ / 128, (B_ * T_) / 128, 3), 256>>>();           // 4
    attn_kernel<<<dim3(T_ / 128, B_ * H_), 512, ATTN_SMEM>>>();               // 5  <- ncu
    gemm_out_kernel<<<gg, 256>>>(bo, out);                                    // 6
}

// round 10
// speedup vs baseline: 1.1104x; 1.1104x over previous
#include <cuda_runtime.h>
#include <cstdint>
#include <math.h>

#define B_  2
#define T_  2048
#define D_  2048
#define H_  32
#define HD_ 64

// ---------------- scratch (no allocation allowed) ----------------
static __device__ int g_mode;
static __device__ __align__(16) int8_t g_hs[B_*T_*D_];
static __device__ __align__(16) int8_t g_Wq[D_*D_];
static __device__ __align__(16) int8_t g_Wk[D_*D_];
static __device__ __align__(16) int8_t g_Wv[D_*D_];
static __device__ __align__(16) int8_t g_Wo[D_*D_];
static __device__ __align__(16) int8_t g_bq[D_];
static __device__ __align__(16) int8_t g_bk[D_];
static __device__ __align__(16) int8_t g_bv[D_];
static __device__ __align__(16) int8_t g_q [B_*T_*D_];
static __device__ __align__(16) int8_t g_k [B_*T_*D_];
static __device__ __align__(16) int8_t g_v [B_*T_*D_];
static __device__ __align__(16) int8_t g_ao[B_*T_*D_];

// ---------------- dtype sniff (proven) ----------------
__global__ void sniff_kernel(const void* __restrict__ p)
{
    __shared__ int s_i32, s_f32;
    if (threadIdx.x == 0) { s_i32 = 1; s_f32 = 1; }
    __syncthreads();
    const int*   wi = (const int*)p;
    const float* wf = (const float*)p;
    int ok_i = 1, ok_f = 1;
    for (int i = threadIdx.x; i < 4096; i += blockDim.x) {
        int v = wi[i];
        if (v < -128 || v > 127) ok_i = 0;
        float f = wf[i];
        if (!(f >= -128.f && f <= 127.f && f == rintf(f))) ok_f = 0;
    }
    if (!ok_i) atomicExch(&s_i32, 0);
    if (!ok_f) atomicExch(&s_f32, 0);
    __syncthreads();
    if (threadIdx.x == 0) g_mode = s_i32 ? 1 : (s_f32 ? 2 : 0);
}

// ---------------- pack ALL 8 inputs in one launch ----------------
__global__ void pack_all_kernel(const void* p0, const void* p1, const void* p2,
                                const void* p3, const void* p4, const void* p5,
                                const void* p6, const void* p7)
{
    const int sel = blockIdx.y;
    const void* in =
        (sel == 0) ? p0 : (sel == 1) ? p1 : (sel == 2) ? p2 : (sel == 3) ? p3 :
        (sel == 4) ? p4 : (sel == 5) ? p5 : (sel == 6) ? p6 : p7;
    int8_t* outp =
        (sel == 0) ? g_hs : (sel == 1) ? g_Wq : (sel == 2) ? g_Wk :
        (sel == 3) ? g_Wv : (sel == 4) ? g_Wo : (sel == 5) ? g_bq :
        (sel == 6) ? g_bk : g_bv;
    const int nwords = (sel == 0) ? (B_*T_*D_/4) : (sel <= 4) ? (D_*D_/4) : (D_/4);
    int* ow = (int*)outp;
    const int mode = g_mode;
    int i = blockIdx.x * blockDim.x + threadIdx.x;
    const int stride = gridDim.x * blockDim.x;
    for (; i < nwords; i += stride) {
        int w;
        if (mode == 0) {
            w = ((const int*)in)[i];
        } else if (mode == 1) {
            int4 v = ((const int4*)in)[i];
            w = (v.x & 255) | ((v.y & 255) << 8) | ((v.z & 255) << 16) | ((v.w & 255) << 24);
        } else {
            float4 v = ((const float4*)in)[i];
            int a = (int)rintf(v.x) & 255, b = (int)rintf(v.y) & 255;
            int c = (int)rintf(v.z) & 255, d = (int)rintf(v.w) & 255;
            w = a | (b << 8) | (c << 16) | (d << 24);
        }
        ow[i] = w;
    }
}

// ---------------- mma / ldmatrix / cp.async helpers ----------------
__device__ __forceinline__ void mma_s8(int& d0, int& d1, int& d2, int& d3,
                                       int a0, int a1, int a2, int a3,
                                       int b0, int b1)
{
    asm volatile(
        "mma.sync.aligned.m16n8k32.row.col.s32.s8.s8.s32 "
        "{%0,%1,%2,%3},{%4,%5,%6,%7},{%8,%9},{%0,%1,%2,%3};\n"
        : "+r"(d0), "+r"(d1), "+r"(d2), "+r"(d3)
        : "r"(a0), "r"(a1), "r"(a2), "r"(a3), "r"(b0), "r"(b1));
}
__device__ __forceinline__ void ldsm4(int& r0, int& r1, int& r2, int& r3, uint32_t a)
{
    asm volatile("ldmatrix.sync.aligned.m8n8.x4.shared.b16 {%0,%1,%2,%3},[%4];\n"
                 : "=r"(r0), "=r"(r1), "=r"(r2), "=r"(r3) : "r"(a));
}
__device__ __forceinline__ void ldsm2(int& r0, int& r1, uint32_t a)
{
    asm volatile("ldmatrix.sync.aligned.m8n8.x2.shared.b16 {%0,%1},[%2];\n"
                 : "=r"(r0), "=r"(r1) : "r"(a));
}
__device__ __forceinline__ void cp16(uint32_t dst, const void* src)
{
    asm volatile("cp.async.cg.shared.global [%0],[%1],16;\n" :: "r"(dst), "l"(src));
}
__device__ __forceinline__ void cp_commit() { asm volatile("cp.async.commit_group;\n"); }
__device__ __forceinline__ void cp_wait0()  { asm volatile("cp.async.wait_group 0;\n"); }
__device__ __forceinline__ uint32_t s2u(const void* p)
{
    return (uint32_t)__cvta_generic_to_shared(p);
}

// ---------------- GEMM body (proven) ----------------
__device__ __forceinline__ void gemm_body(const float* __restrict__ bias_f,
                                          float alpha, float* __restrict__ outf,
                                          int zsel)
{
    __shared__ int As[2][128 * 20];
    __shared__ int Bs[2][128 * 20];

    const int tid = threadIdx.x, w = tid >> 5, lane = tid & 31;
    const int g = lane >> 2, tg = lane & 3;
    const int wm = w >> 2, wn = w & 3;
    const int m0 = blockIdx.y * 128, n0 = blockIdx.x * 128;

    const int4* X4 = (const int4*)((zsel == 3) ? (const void*)g_ao : (const void*)g_hs);
    const int4* W4 = (const int4*)((zsel == 0) ? (const void*)g_Wq :
                                   (zsel == 1) ? (const void*)g_Wk :
                                   (zsel == 2) ? (const void*)g_Wv : (const void*)g_Wo);

    const uint32_t asb = s2u(&As[0][0]);
    const uint32_t bsb = s2u(&Bs[0][0]);

    const uint32_t a_lrow = (uint32_t)(lane & 15);
    const uint32_t a_khalf = (uint32_t)(lane >> 4);
    const uint32_t offA = (uint32_t)((wm * 64 + a_lrow) * 20 + a_khalf * 4) * 4;
    const uint32_t b_lrow = (uint32_t)(lane & 7);
    const uint32_t b_khalf = (uint32_t)((lane >> 3) & 1);
    const uint32_t offB = (uint32_t)((wn * 32 + b_lrow) * 20 + b_khalf * 4) * 4;

    const int r_a = tid >> 2, c4_a = tid & 3;
    const int r_b = (tid + 256) >> 2;

    int acc[4][4][4];
    #pragma unroll
    for (int mt = 0; mt < 4; mt++)
        #pragma unroll
        for (int nt = 0; nt < 4; nt++)
            #pragma unroll
            for (int i = 0; i < 4; i++) acc[mt][nt][i] = 0;

    auto issue = [&](int kt, int buf) {
        uint32_t ab = asb + (uint32_t)buf * 128 * 20 * 4;
        uint32_t bb = bsb + (uint32_t)buf * 128 * 20 * 4;
        cp16(ab + (uint32_t)(r_a * 20 + c4_a * 4) * 4, X4 + (size_t)(m0 + r_a) * 128 + kt * 4 + c4_a);
        cp16(ab + (uint32_t)(r_b * 20 + c4_a * 4) * 4, X4 + (size_t)(m0 + r_b) * 128 + kt * 4 + c4_a);
        cp16(bb + (uint32_t)(r_a * 20 + c4_a * 4) * 4, W4 + (size_t)(n0 + r_a) * 128 + kt * 4 + c4_a);
        cp16(bb + (uint32_t)(r_b * 20 + c4_a * 4) * 4, W4 + (size_t)(n0 + r_b) * 128 + kt * 4 + c4_a);
        cp_commit();
    };

    issue(0, 0);
    for (int kt = 0; kt < 32; ++kt) {
        cp_wait0();
        __syncthreads();
        if (kt < 31) issue(kt + 1, (kt + 1) & 1);
        const uint32_t abuf = asb + (uint32_t)(kt & 1) * 128 * 20 * 4;
        const uint32_t bbuf = bsb + (uint32_t)(kt & 1) * 128 * 20 * 4;
        #pragma unroll
        for (int ks = 0; ks < 2; ++ks) {
            int a[4][4];
            #pragma unroll
            for (int mt = 0; mt < 4; mt++)
                ldsm4(a[mt][0], a[mt][1], a[mt][2], a[mt][3],
                      abuf + offA + (uint32_t)(mt * 16 * 20 + ks * 8) * 4);
            #pragma unroll
            for (int nt = 0; nt < 4; nt++) {
                int b0, b1;
                ldsm2(b0, b1, bbuf + offB + (uint32_t)(nt * 8 * 20 + ks * 8) * 4);
                #pragma unroll
                for (int mt = 0; mt < 4; mt++)
                    mma_s8(acc[mt][nt][0], acc[mt][nt][1], acc[mt][nt][2], acc[mt][nt][3],
                           a[mt][0], a[mt][1], a[mt][2], a[mt][3], b0, b1);
            }
        }
    }

    if (zsel < 3) {
        const int8_t* bi = (zsel == 0) ? g_bq : (zsel == 1) ? g_bk : g_bv;
        int8_t* Y = (zsel == 0) ? g_q : (zsel == 1) ? g_k : g_v;
        #pragma unroll
        for (int nt = 0; nt < 4; nt++) {
            int col = n0 + wn * 32 + nt * 8 + 2 * tg;
            float bb0 = (float)bi[col], bb1 = (float)bi[col + 1];
            #pragma unroll
            for (int mt = 0; mt < 4; mt++) {
                int r = m0 + wm * 64 + mt * 16 + g;
                #pragma unroll
                for (int half = 0; half < 2; half++) {
                    int rr = r + half * 8;
                    float y0 = __fadd_rn(__fmul_rn(alpha, (float)acc[mt][nt][half * 2 + 0]), bb0);
                    float y1 = __fadd_rn(__fmul_rn(alpha, (float)acc[mt][nt][half * 2 + 1]), bb1);
                    int q0 = max(-128, min(127, (int)rintf(y0)));
                    int q1 = max(-128, min(127, (int)rintf(y1)));
                    *(short*)&Y[(size_t)rr * D_ + col] = (short)((q0 & 255) | ((q1 & 255) << 8));
                }
            }
        }
    } else {
        #pragma unroll
        for (int nt = 0; nt < 4; nt++) {
            int col = n0 + wn * 32 + nt * 8 + 2 * tg;
            float bb0 = bias_f[col], bb1 = bias_f[col + 1];
            #pragma unroll
            for (int mt = 0; mt < 4; mt++) {
                int r = m0 + wm * 64 + mt * 16 + g;
                #pragma unroll
                for (int half = 0; half < 2; half++) {
                    int rr = r + half * 8;
                    float y0 = __fadd_rn(__fmul_rn(alpha, (float)acc[mt][nt][half * 2 + 0]), bb0);
                    float y1 = __fadd_rn(__fmul_rn(alpha, (float)acc[mt][nt][half * 2 + 1]), bb1);
                    *(float2*)&outf[(size_t)rr * D_ + col] = make_float2(y0, y1);
                }
            }
        }
    }
}

__global__ __launch_bounds__(256, 2) void gemm_qkv_kernel()
{
    gemm_body(nullptr, 3e-4f, nullptr, (int)blockIdx.z);
}
__global__ __launch_bounds__(256, 2) void gemm_out_kernel(const float* __restrict__ bo,
                                                          float* __restrict__ out)
{
    gemm_body(bo, 1e-4f, out, 3);
}

// ---------------- fused attention, 64 q-rows, 256 thr, max-free softmax ----------------
// |score| <= 2e-5 * 64*128*128 ~= 21  =>  exp(score) in [7.6e-10, 1.3e9]: fp32-safe
// without max subtraction (softmax is shift-invariant; reference parity to ~ulp).
__global__ __launch_bounds__(256, 2) void attn_kernel()
{
    const float A_QK = 2e-5f, A_PV = 1e-2f;
    const int bh = blockIdx.y, b = bh >> 5, h = bh & 31;
    const int r0 = blockIdx.x * 64;
    const int tid = threadIdx.x, w = tid >> 5, lane = tid & 31;
    const int g = lane >> 2, tg = lane & 3;
    const int wm = w & 3, wn = w >> 2;

    __shared__ int   qs[64 * 20];
    __shared__ int   ks[128 * 20];
    __shared__ int   vraw[128 * 20];
    __shared__ int   vT[64 * 36];
    __shared__ int   ps[64 * 36];
    __shared__ float redl[2][64];
    __shared__ float rowRL[64];

    const int4* Q4 = (const int4*)g_q;
    const int4* K4 = (const int4*)g_k;
    const int4* V4 = (const int4*)g_v;

    const uint32_t qsb = s2u(&qs[0]);
    const uint32_t ksb = s2u(&ks[0]);
    const uint32_t psb32 = s2u(&ps[0]);
    const uint32_t vtb = s2u(&vT[0]);

    const uint32_t a_lrow = (uint32_t)(lane & 15);
    const uint32_t a_khalf = (uint32_t)(lane >> 4);
    const uint32_t offQ  = (uint32_t)((wm * 16 + a_lrow) * 20 + a_khalf * 4) * 4;
    const uint32_t offPs = (uint32_t)((wm * 16 + a_lrow) * 36 + a_khalf * 4) * 4;
    const uint32_t b_lrow = (uint32_t)(lane & 7);
    const uint32_t b_khalf = (uint32_t)((lane >> 3) & 1);
    const uint32_t offK  = (uint32_t)(b_lrow * 20 + b_khalf * 4) * 4;
    const uint32_t offVt = (uint32_t)(b_lrow * 36 + b_khalf * 4) * 4;

    {
        int row = tid >> 2, c4 = tid & 3;
        *(int4*)&qs[row * 20 + c4 * 4] = Q4[(size_t)(b * T_ + r0 + row) * 128 + h * 4 + c4];
    }

    const int nch = ((r0 + 63) >> 7) + 1;
    const int tA = r0 + wm * 16 + g, tB = tA + 8;

    // ---------- pass A: row sums of exp(score) ----------
    float lA = 0.f, lB = 0.f;
    for (int c = 0; c < nch; ++c) {
        const int s0 = c << 7;
        {
            int ra = tid >> 2, ca = tid & 3, rb = (tid + 256) >> 2;
            *(int4*)&ks[ra * 20 + ca * 4] = K4[(size_t)(b * T_ + s0 + ra) * 128 + h * 4 + ca];
            *(int4*)&ks[rb * 20 + ca * 4] = K4[(size_t)(b * T_ + s0 + rb) * 128 + h * 4 + ca];
        }
        __syncthreads();

        int cc[8][4];
        #pragma unroll
        for (int nt = 0; nt < 8; nt++)
            #pragma unroll
            for (int i = 0; i < 4; i++) cc[nt][i] = 0;
        #pragma unroll
        for (int ksi = 0; ksi < 2; ++ksi) {
            int a0, a1, a2, a3;
            ldsm4(a0, a1, a2, a3, qsb + offQ + (uint32_t)(ksi * 8) * 4);
            #pragma unroll
            for (int nt = 0; nt < 8; nt++) {
                int b0, b1;
                ldsm2(b0, b1, ksb + offK + (uint32_t)((wn * 64 + nt * 8) * 20 + ksi * 8) * 4);
                mma_s8(cc[nt][0], cc[nt][1], cc[nt][2], cc[nt][3], a0, a1, a2, a3, b0, b1);
            }
        }
        if (c < nch - 1) {
            // fully causal-visible chunk: branch-free accumulation
            #pragma unroll
            for (int nt = 0; nt < 8; nt++) {
                lA += __expf(__fmul_rn(A_QK, (float)cc[nt][0]))
                    + __expf(__fmul_rn(A_QK, (float)cc[nt][1]));
                lB += __expf(__fmul_rn(A_QK, (float)cc[nt][2]))
                    + __expf(__fmul_rn(A_QK, (float)cc[nt][3]));
            }
        } else {
            #pragma unroll
            for (int nt = 0; nt < 8; nt++) {
                int scol = s0 + wn * 64 + nt * 8 + 2 * tg;
                #pragma unroll
                for (int e = 0; e < 2; e++) {
                    int s = scol + e;
                    if (s <= tA) lA += __expf(__fmul_rn(A_QK, (float)cc[nt][e]));
                    if (s <= tB) lB += __expf(__fmul_rn(A_QK, (float)cc[nt][2 + e]));
                }
            }
        }
        __syncthreads();
    }
    // sum across the 4 tg lanes
    #pragma unroll
    for (int d = 1; d < 4; d <<= 1) {
        lA += __shfl_xor_sync(0xffffffffu, lA, d);
        lB += __shfl_xor_sync(0xffffffffu, lB, d);
    }
    if (tg == 0) {
        redl[wn][wm * 16 + g] = lA;
        redl[wn][wm * 16 + g + 8] = lB;
    }
    __syncthreads();
    if (tid < 64) rowRL[tid] = 127.0f / (redl[0][tid] + redl[1][tid]);
    __syncthreads();

    const float RA = rowRL[wm * 16 + g];
    const float RB = rowRL[wm * 16 + g + 8];

    // ---------- pass B: recompute scores, quantize p, PV ----------
    int oacc[4][4];
    #pragma unroll
    for (int nt = 0; nt < 4; nt++)
        #pragma unroll
        for (int i = 0; i < 4; i++) oacc[nt][i] = 0;

    for (int c = 0; c < nch; ++c) {
        const int s0 = c << 7;
        {
            int ra = tid >> 2, ca = tid & 3, rb = (tid + 256) >> 2;
            size_t base_a = (size_t)(b * T_ + s0 + ra) * 128 + h * 4 + ca;
            size_t base_b = (size_t)(b * T_ + s0 + rb) * 128 + h * 4 + ca;
            *(int4*)&ks[ra * 20 + ca * 4]   = K4[base_a];
            *(int4*)&ks[rb * 20 + ca * 4]   = K4[base_b];
            *(int4*)&vraw[ra * 20 + ca * 4] = V4[base_a];
            *(int4*)&vraw[rb * 20 + ca * 4] = V4[base_b];
        }
        __syncthreads();

        int cc[8][4];
        #pragma unroll
        for (int nt = 0; nt < 8; nt++)
            #pragma unroll
            for (int i = 0; i < 4; i++) cc[nt][i] = 0;
        #pragma unroll
        for (int ksi = 0; ksi < 2; ++ksi) {
            int a0, a1, a2, a3;
            ldsm4(a0, a1, a2, a3, qsb + offQ + (uint32_t)(ksi * 8) * 4);
            #pragma unroll
            for (int nt = 0; nt < 8; nt++) {
                int b0, b1;
                ldsm2(b0, b1, ksb + offK + (uint32_t)((wn * 64 + nt * 8) * 20 + ksi * 8) * 4);
                mma_s8(cc[nt][0], cc[nt][1], cc[nt][2], cc[nt][3], a0, a1, a2, a3, b0, b1);
            }
        }
        char* psb = (char*)ps;
        if (c < nch - 1) {
            #pragma unroll
            for (int nt = 0; nt < 8; nt++) {
                int col = wn * 64 + nt * 8 + 2 * tg;
                int pA0 = min(127, (int)rintf(__expf(__fmul_rn(A_QK, (float)cc[nt][0])) * RA));
                int pA1 = min(127, (int)rintf(__expf(__fmul_rn(A_QK, (float)cc[nt][1])) * RA));
                int pB0 = min(127, (int)rintf(__expf(__fmul_rn(A_QK, (float)cc[nt][2])) * RB));
                int pB1 = min(127, (int)rintf(__expf(__fmul_rn(A_QK, (float)cc[nt][3])) * RB));
                *(short*)(psb + (wm * 16 + g) * 144 + col)     = (short)(pA0 | (pA1 << 8));
                *(short*)(psb + (wm * 16 + g + 8) * 144 + col) = (short)(pB0 | (pB1 << 8));
            }
        } else {
            #pragma unroll
            for (int nt = 0; nt < 8; nt++) {
                int col = wn * 64 + nt * 8 + 2 * tg;
                int scol = s0 + col;
                int pA0 = 0, pA1 = 0, pB0 = 0, pB1 = 0;
                if (scol <= tA)
                    pA0 = min(127, (int)rintf(__expf(__fmul_rn(A_QK, (float)cc[nt][0])) * RA));
                if (scol + 1 <= tA)
                    pA1 = min(127, (int)rintf(__expf(__fmul_rn(A_QK, (float)cc[nt][1])) * RA));
                if (scol <= tB)
                    pB0 = min(127, (int)rintf(__expf(__fmul_rn(A_QK, (float)cc[nt][2])) * RB));
                if (scol + 1 <= tB)
                    pB1 = min(127, (int)rintf(__expf(__fmul_rn(A_QK, (float)cc[nt][3])) * RB));
                *(short*)(psb + (wm * 16 + g) * 144 + col)     = (short)(pA0 | (pA1 << 8));
                *(short*)(psb + (wm * 16 + g + 8) * 144 + col) = (short)(pB0 | (pB1 << 8));
            }
        }
        // transpose-pack V: vT[d][sw] packs v[s0+4sw..+3][d]
        #pragma unroll
        for (int k = 0; k < 8; ++k) {
            int idx = k * 256 + tid;
            int d = idx >> 5, sw = idx & 31;
            int cword = d >> 2, csh = (d & 3) * 8;
            unsigned wd = 0;
            #pragma unroll
            for (int z = 0; z < 4; ++z) {
                unsigned by = ((unsigned)vraw[(4 * sw + z) * 20 + cword] >> csh) & 255u;
                wd |= by << (8 * z);
            }
            vT[d * 36 + sw] = (int)wd;
        }
        __syncthreads();

        #pragma unroll
        for (int kk = 0; kk < 4; ++kk) {
            int a0, a1, a2, a3;
            ldsm4(a0, a1, a2, a3, psb32 + offPs + (uint32_t)(kk * 8) * 4);
            #pragma unroll
            for (int nt = 0; nt < 4; nt++) {
                int b0, b1;
                ldsm2(b0, b1, vtb + offVt + (uint32_t)((wn * 32 + nt * 8) * 36 + kk * 8) * 4);
                mma_s8(oacc[nt][0], oacc[nt][1], oacc[nt][2], oacc[nt][3],
                       a0, a1, a2, a3, b0, b1);
            }
        }
        __syncthreads();
    }

    #pragma unroll
    for (int nt = 0; nt < 4; nt++) {
        int col = h * HD_ + wn * 32 + nt * 8 + 2 * tg;
        float yA0 = __fmul_rn(A_PV, (float)oacc[nt][0]);
        float yA1 = __fmul_rn(A_PV, (float)oacc[nt][1]);
        float yB0 = __fmul_rn(A_PV, (float)oacc[nt][2]);
        float yB1 = __fmul_rn(A_PV, (float)oacc[nt][3]);
        int qA0 = max(-128, min(127, (int)rintf(yA0)));
        int qA1 = max(-128, min(127, (int)rintf(yA1)));
        int qB0 = max(-128, min(127, (int)rintf(yB0)));
        int qB1 = max(-128, min(127, (int)rintf(yB1)));
        *(short*)&g_ao[(size_t)(b * T_ + tA) * D_ + col] = (short)((qA0 & 255) | ((qA1 & 255) << 8));
        *(short*)&g_ao[(size_t)(b * T_ + tB) * D_ + col] = (short)((qB0 & 255) | ((qB1 & 255) << 8));
    }
}

// ---------------- launch ----------------
extern "C" void kernel_launch(void* const* d_in, const int* in_sizes, int n_in,
                              void* d_out, int out_size)
{
    (void)n_in; (void)out_size;
    int i_hs, i_Wq, i_bq, i_Wk, i_bk, i_Wv, i_bv, i_Wo, i_bo;
    if (in_sizes[0] == 4194304) {          // alphabetical
        i_Wk = 0; i_Wo = 1; i_Wq = 2; i_Wv = 3;
        i_bk = 5; i_bo = 6; i_bq = 7; i_bv = 8; i_hs = 9;
    } else {                                // dict / signature order
        i_hs = 0; i_Wq = 2; i_bq = 3; i_Wk = 4; i_bk = 5;
        i_Wv = 6; i_bv = 7; i_Wo = 8; i_bo = 9;
    }
    const float* bo = (const float*)d_in[i_bo];
    float* out = (float*)d_out;

    // ncu empirically captures the 4th launch -> attn_kernel
    sniff_kernel<<<1, 256>>>(d_in[i_hs]);                                     // 1
    pack_all_kernel<<<dim3(512, 8), 256>>>(d_in[i_hs], d_in[i_Wq], d_in[i_Wk],
                                           d_in[i_Wv], d_in[i_Wo], d_in[i_bq],
                                           d_in[i_bk], d_in[i_bv]);           // 2
    gemm_qkv_kernel<<<dim3(D_ / 128, (B_ * T_) / 128, 3), 256>>>();           // 3
    attn_kernel<<<dim3(T_ / 64, B_ * H_), 256>>>();                           // 4  <- ncu
    gemm_out_kernel<<<dim3(D_ / 128, (B_ * T_) / 128), 256>>>(bo, out);       // 5
}